// round 3
// baseline (speedup 1.0000x reference)
#include <cuda_runtime.h>
#include <cuda_bf16.h>

// out = W - c * K^T (K W - V)
// W: (4096,4096) f32, K: (512,4096) f32, V: (512,4096) f32
// c = 2*0.1/(512*4096)

#define D 4096
#define CTX 512
#define BM 128
#define BN 128
#define BK 16

__device__ float g_P[CTX * D];  // scratch for P = K@W - V (8 MB)

// ---------------------------------------------------------------------------
// GEMM1: P[c][j] = sum_k K[c][k] * W[k][j] - V[c][j]
// grid: (D/BN, CTX/BM) = (32, 4), 256 threads
// ---------------------------------------------------------------------------
__global__ __launch_bounds__(256) void gemm1_kernel(
    const float* __restrict__ Kmat,
    const float* __restrict__ Wmat,
    const float* __restrict__ Vmat,
    float* __restrict__ Pmat)
{
    __shared__ float As[BK][BM];
    __shared__ float Bs[BK][BN];

    const int j0 = blockIdx.x * BN;
    const int c0 = blockIdx.y * BM;
    const int tid = threadIdx.x;
    const int tm = (tid >> 4) * 8;   // row offset within tile (c)
    const int tn = (tid & 15) * 8;   // col offset within tile (j)

    float acc[8][8];
#pragma unroll
    for (int i = 0; i < 8; i++)
#pragma unroll
        for (int j = 0; j < 8; j++) acc[i][j] = 0.f;

    for (int kt = 0; kt < D; kt += BK) {
        // Load A tile: K[c0+r][kt+kk], 128x16, transposed into As[kk][r]
#pragma unroll
        for (int t = 0; t < 2; t++) {
            int idx = tid + t * 256;        // 0..511
            int r = idx >> 2;               // 0..127
            int kk4 = (idx & 3) * 4;        // 0,4,8,12
            float4 v = *(const float4*)&Kmat[(size_t)(c0 + r) * D + kt + kk4];
            As[kk4 + 0][r] = v.x;
            As[kk4 + 1][r] = v.y;
            As[kk4 + 2][r] = v.z;
            As[kk4 + 3][r] = v.w;
        }
        // Load B tile: W[kt+row][j0+col], 16x128, direct
#pragma unroll
        for (int t = 0; t < 2; t++) {
            int idx = tid + t * 256;
            int row = idx >> 5;             // 0..15
            int col4 = (idx & 31) * 4;      // 0..124
            *(float4*)&Bs[row][col4] =
                *(const float4*)&Wmat[(size_t)(kt + row) * D + j0 + col4];
        }
        __syncthreads();

#pragma unroll
        for (int kk = 0; kk < BK; kk++) {
            float a[8], b[8];
#pragma unroll
            for (int i = 0; i < 8; i++) a[i] = As[kk][tm + i];
#pragma unroll
            for (int j = 0; j < 8; j++) b[j] = Bs[kk][tn + j];
#pragma unroll
            for (int i = 0; i < 8; i++)
#pragma unroll
                for (int j = 0; j < 8; j++) acc[i][j] += a[i] * b[j];
        }
        __syncthreads();
    }

    // Epilogue: P = acc - V
#pragma unroll
    for (int i = 0; i < 8; i++) {
        int row = c0 + tm + i;
#pragma unroll
        for (int j = 0; j < 8; j += 4) {
            int col = j0 + tn + j;
            float4 v = *(const float4*)&Vmat[(size_t)row * D + col];
            float4 o;
            o.x = acc[i][j + 0] - v.x;
            o.y = acc[i][j + 1] - v.y;
            o.z = acc[i][j + 2] - v.z;
            o.w = acc[i][j + 3] - v.w;
            *(float4*)&Pmat[(size_t)row * D + col] = o;
        }
    }
}

// ---------------------------------------------------------------------------
// GEMM2: out[i][j] = W[i][j] - c * sum_k K[k][i] * P[k][j]
// grid: (D/BN, D/BM) = (32, 32), 256 threads
// A = K^T: A[i][k] = K[k][i]; K row-major means the [BK][BM] tile of A
// is a contiguous row-segment load per k — naturally coalesced, no transpose.
// ---------------------------------------------------------------------------
__global__ __launch_bounds__(256) void gemm2_kernel(
    const float* __restrict__ Kmat,
    const float* __restrict__ Pmat,
    const float* __restrict__ Wmat,
    float* __restrict__ Out,
    float scale)
{
    __shared__ float As[BK][BM];
    __shared__ float Bs[BK][BN];

    const int j0 = blockIdx.x * BN;
    const int i0 = blockIdx.y * BM;
    const int tid = threadIdx.x;
    const int tm = (tid >> 4) * 8;
    const int tn = (tid & 15) * 8;

    float acc[8][8];
#pragma unroll
    for (int i = 0; i < 8; i++)
#pragma unroll
        for (int j = 0; j < 8; j++) acc[i][j] = 0.f;

    for (int kt = 0; kt < CTX; kt += BK) {
        // A tile: As[kk][r] = K[kt+kk][i0+r]  (contiguous along r)
#pragma unroll
        for (int t = 0; t < 2; t++) {
            int idx = tid + t * 256;
            int kk = idx >> 5;              // 0..15
            int r4 = (idx & 31) * 4;        // 0..124
            *(float4*)&As[kk][r4] =
                *(const float4*)&Kmat[(size_t)(kt + kk) * D + i0 + r4];
        }
        // B tile: Bs[kk][col] = P[kt+kk][j0+col]
#pragma unroll
        for (int t = 0; t < 2; t++) {
            int idx = tid + t * 256;
            int kk = idx >> 5;
            int col4 = (idx & 31) * 4;
            *(float4*)&Bs[kk][col4] =
                *(const float4*)&Pmat[(size_t)(kt + kk) * D + j0 + col4];
        }
        __syncthreads();

#pragma unroll
        for (int kk = 0; kk < BK; kk++) {
            float a[8], b[8];
#pragma unroll
            for (int i = 0; i < 8; i++) a[i] = As[kk][tm + i];
#pragma unroll
            for (int j = 0; j < 8; j++) b[j] = Bs[kk][tn + j];
#pragma unroll
            for (int i = 0; i < 8; i++)
#pragma unroll
                for (int j = 0; j < 8; j++) acc[i][j] += a[i] * b[j];
        }
        __syncthreads();
    }

    // Epilogue: out = W - scale * acc
#pragma unroll
    for (int i = 0; i < 8; i++) {
        int row = i0 + tm + i;
#pragma unroll
        for (int j = 0; j < 8; j += 4) {
            int col = j0 + tn + j;
            float4 w = *(const float4*)&Wmat[(size_t)row * D + col];
            float4 o;
            o.x = w.x - scale * acc[i][j + 0];
            o.y = w.y - scale * acc[i][j + 1];
            o.z = w.z - scale * acc[i][j + 2];
            o.w = w.w - scale * acc[i][j + 3];
            *(float4*)&Out[(size_t)row * D + col] = o;
        }
    }
}

extern "C" void kernel_launch(void* const* d_in, const int* in_sizes, int n_in,
                              void* d_out, int out_size)
{
    const float* Wmat = (const float*)d_in[0];   // (4096, 4096)
    const float* Kmat = (const float*)d_in[1];   // (512, 4096)
    const float* Vmat = (const float*)d_in[2];   // (512, 4096)
    float* Out = (float*)d_out;                  // (4096, 4096)

    float* Pmat = nullptr;
    cudaGetSymbolAddress((void**)&Pmat, g_P);

    const float scale = 2.0f * 0.1f / ((float)CTX * (float)D);

    dim3 grid1(D / BN, CTX / BM);   // (32, 4)
    gemm1_kernel<<<grid1, 256>>>(Kmat, Wmat, Vmat, Pmat);

    dim3 grid2(D / BN, D / BM);     // (32, 32)
    gemm2_kernel<<<grid2, 256>>>(Kmat, Pmat, Wmat, Out, scale);
}

// round 5
// speedup vs baseline: 5.4032x; 5.4032x over previous
#include <cuda_runtime.h>
#include <cuda_bf16.h>
#include <cstdint>

// out = W - c * K^T (K W - V),  c = 2*0.1/(CTX*D)
// W: (4096,4096) f32, K: (512,4096) f32, V: (512,4096) f32
#define D 4096
#define CTX 512

// scratch (device globals -- no allocation allowed)
__device__ __align__(16) __nv_bfloat16 g_Kb[CTX * D];       // bf16 K    (4 MB)
__device__ __align__(16) __nv_bfloat16 g_Wb[(size_t)D * D]; // bf16 W    (32 MB)
__device__ __align__(16) __nv_bfloat16 g_P[CTX * D];        // bf16 KW-V (4 MB)

// ---------------------------------------------------------------------------
// helpers (baseline PTX only -- the harness targets sm_103 without 'a')
// ---------------------------------------------------------------------------
__device__ __forceinline__ uint32_t smem_u32(const void* p) {
    uint32_t a;
    asm("{ .reg .u64 t; cvta.to.shared.u64 t, %1; cvt.u32.u64 %0, t; }" : "=r"(a) : "l"(p));
    return a;
}
#define CP16(s, g)   asm volatile("cp.async.cg.shared.global [%0], [%1], 16;" :: "r"(s), "l"(g))
#define CP_COMMIT()  asm volatile("cp.async.commit_group;" ::: "memory")
#define CP_WAIT0()   asm volatile("cp.async.wait_group 0;" ::: "memory")

__device__ __forceinline__ void ldsm_x4(uint32_t (&r)[4], uint32_t a) {
    asm volatile("ldmatrix.sync.aligned.m8n8.x4.shared.b16 {%0,%1,%2,%3}, [%4];"
                 : "=r"(r[0]), "=r"(r[1]), "=r"(r[2]), "=r"(r[3]) : "r"(a));
}
__device__ __forceinline__ void ldsm_x4t(uint32_t (&r)[4], uint32_t a) {
    asm volatile("ldmatrix.sync.aligned.m8n8.x4.trans.shared.b16 {%0,%1,%2,%3}, [%4];"
                 : "=r"(r[0]), "=r"(r[1]), "=r"(r[2]), "=r"(r[3]) : "r"(a));
}
__device__ __forceinline__ void mma16816(float (&d)[4], const uint32_t (&a)[4],
                                         uint32_t b0, uint32_t b1) {
    asm volatile("mma.sync.aligned.m16n8k16.row.col.f32.bf16.bf16.f32 "
                 "{%0,%1,%2,%3}, {%4,%5,%6,%7}, {%8,%9}, {%0,%1,%2,%3};"
                 : "+f"(d[0]), "+f"(d[1]), "+f"(d[2]), "+f"(d[3])
                 : "r"(a[0]), "r"(a[1]), "r"(a[2]), "r"(a[3]), "r"(b0), "r"(b1));
}

// ---------------------------------------------------------------------------
// prep: f32 -> bf16 (8 elems/thread)
// ---------------------------------------------------------------------------
__global__ void convert_kernel(const float4* __restrict__ src, __nv_bfloat162* __restrict__ dst) {
    int i = blockIdx.x * blockDim.x + threadIdx.x;
    float4 a = src[2 * i], b = src[2 * i + 1];
    dst[4 * i + 0] = __float22bfloat162_rn(make_float2(a.x, a.y));
    dst[4 * i + 1] = __float22bfloat162_rn(make_float2(a.z, a.w));
    dst[4 * i + 2] = __float22bfloat162_rn(make_float2(b.x, b.y));
    dst[4 * i + 3] = __float22bfloat162_rn(make_float2(b.z, b.w));
}

// smem strides (elements): A1 tile [128 m][32 k] pad->40 ; [k][x] tiles [32][128] pad->136
#define SA1 40
#define SKX 136
#define ST1_BYTES (128 * SA1 * 2 + 32 * SKX * 2)   // 10240 + 8704 = 18944
#define ST2_BYTES (2 * 32 * SKX * 2)               // 17408

// ---------------------------------------------------------------------------
// GEMM1: P[c][n] = bf16( sum_k K[c][k] W[k][n] - V[c][n] )
// A = Kb [m][k] (non-trans), B = Wb [k][n] (trans).  grid (32,4), 256 thr
// ---------------------------------------------------------------------------
__global__ __launch_bounds__(256) void gemm1_mma(
    const __nv_bfloat16* __restrict__ Kb, const __nv_bfloat16* __restrict__ Wb,
    const float* __restrict__ Vmat, __nv_bfloat16* __restrict__ P)
{
    extern __shared__ __align__(16) char sm[];
    const int tid = threadIdx.x, lane = tid & 31, wid = tid >> 5;
    const int j0 = blockIdx.x * 128, c0 = blockIdx.y * 128;
    const int wm = (wid >> 2) * 64, wn = (wid & 3) * 32;

    float acc[4][4][4];
#pragma unroll
    for (int mt = 0; mt < 4; mt++)
#pragma unroll
        for (int nt = 0; nt < 4; nt++)
#pragma unroll
            for (int e = 0; e < 4; e++) acc[mt][nt][e] = 0.f;

    // loaders: 2 chunks each for A and B per thread
    auto load_stage = [&](int stage, int k0) {
        char* tA = sm + stage * ST1_BYTES;
        char* tB = tA + 128 * SA1 * 2;
#pragma unroll
        for (int i = 0; i < 2; i++) {
            int c = tid + i * 256;                 // 0..511
            int m = c >> 2, part = c & 3;          // A: 4 x 16B per m-row
            CP16(smem_u32(tA + (m * SA1 + part * 8) * 2),
                 Kb + (size_t)(c0 + m) * D + k0 + part * 8);
        }
#pragma unroll
        for (int i = 0; i < 2; i++) {
            int c = tid + i * 256;
            int kk = c >> 4, part = c & 15;        // B: 16 x 16B per k-row
            CP16(smem_u32(tB + (kk * SKX + part * 8) * 2),
                 Wb + (size_t)(k0 + kk) * D + j0 + part * 8);
        }
    };

    load_stage(0, 0);
    CP_COMMIT();

    const int NIT = D / 32;  // 128
#pragma unroll 1
    for (int it = 0; it < NIT; it++) {
        CP_WAIT0();
        __syncthreads();
        if (it + 1 < NIT) { load_stage((it + 1) & 1, (it + 1) * 32); CP_COMMIT(); }

        char* tA = sm + (it & 1) * ST1_BYTES;
        char* tB = tA + 128 * SA1 * 2;
#pragma unroll
        for (int ks = 0; ks < 2; ks++) {
            int kk = ks * 16;
            uint32_t af[4][4];
#pragma unroll
            for (int mt = 0; mt < 4; mt++) {
                int m = wm + mt * 16 + (lane & 15);
                int cc = kk + ((lane >> 4) << 3);
                ldsm_x4(af[mt], smem_u32(tA + (m * SA1 + cc) * 2));
            }
            uint32_t bfr[2][4];
#pragma unroll
            for (int nh = 0; nh < 2; nh++) {
                int krow = kk + (lane & 7) + ((lane >> 3) & 1) * 8;
                int ncol = wn + nh * 16 + ((lane >> 4) & 1) * 8;
                ldsm_x4t(bfr[nh], smem_u32(tB + (krow * SKX + ncol) * 2));
            }
#pragma unroll
            for (int mt = 0; mt < 4; mt++)
#pragma unroll
                for (int nt = 0; nt < 4; nt++)
                    mma16816(acc[mt][nt], af[mt], bfr[nt >> 1][(nt & 1) * 2],
                             bfr[nt >> 1][(nt & 1) * 2 + 1]);
        }
    }

    // epilogue: P = bf16(acc - V), direct stores
    const int tq = lane >> 2, tr = lane & 3;
#pragma unroll
    for (int mt = 0; mt < 4; mt++) {
#pragma unroll
        for (int nt = 0; nt < 4; nt++) {
            int row0 = c0 + wm + mt * 16 + tq;
            int col = j0 + wn + nt * 8 + tr * 2;
            float2 v0 = *(const float2*)&Vmat[(size_t)row0 * D + col];
            float2 v1 = *(const float2*)&Vmat[(size_t)(row0 + 8) * D + col];
            __nv_bfloat162 p0, p1;
            p0.x = __float2bfloat16(acc[mt][nt][0] - v0.x);
            p0.y = __float2bfloat16(acc[mt][nt][1] - v0.y);
            p1.x = __float2bfloat16(acc[mt][nt][2] - v1.x);
            p1.y = __float2bfloat16(acc[mt][nt][3] - v1.y);
            *(__nv_bfloat162*)&P[(size_t)row0 * D + col] = p0;
            *(__nv_bfloat162*)&P[(size_t)(row0 + 8) * D + col] = p1;
        }
    }
}

// ---------------------------------------------------------------------------
// GEMM2: out[i][j] = W[i][j] - scale * sum_c K[c][i] P[c][j]
// A = Kb [k][m] (trans), B = P [k][n] (trans).  grid (32,32), 256 thr
// ---------------------------------------------------------------------------
__global__ __launch_bounds__(256) void gemm2_mma(
    const __nv_bfloat16* __restrict__ Kb, const __nv_bfloat16* __restrict__ P,
    const float* __restrict__ Wmat, float* __restrict__ Out, float scale)
{
    extern __shared__ __align__(16) char sm[];
    const int tid = threadIdx.x, lane = tid & 31, wid = tid >> 5;
    const int j0 = blockIdx.x * 128, i0 = blockIdx.y * 128;
    const int wm = (wid >> 2) * 64, wn = (wid & 3) * 32;

    float acc[4][4][4];
#pragma unroll
    for (int mt = 0; mt < 4; mt++)
#pragma unroll
        for (int nt = 0; nt < 4; nt++)
#pragma unroll
            for (int e = 0; e < 4; e++) acc[mt][nt][e] = 0.f;

    auto load_stage = [&](int stage, int k0) {
        char* tA = sm + stage * ST2_BYTES;
        char* tB = tA + 32 * SKX * 2;
#pragma unroll
        for (int i = 0; i < 2; i++) {
            int c = tid + i * 256;
            int kk = c >> 4, part = c & 15;
            CP16(smem_u32(tA + (kk * SKX + part * 8) * 2),
                 Kb + (size_t)(k0 + kk) * D + i0 + part * 8);
        }
#pragma unroll
        for (int i = 0; i < 2; i++) {
            int c = tid + i * 256;
            int kk = c >> 4, part = c & 15;
            CP16(smem_u32(tB + (kk * SKX + part * 8) * 2),
                 P + (size_t)(k0 + kk) * D + j0 + part * 8);
        }
    };

    load_stage(0, 0);
    CP_COMMIT();

    const int NIT = CTX / 32;  // 16
#pragma unroll 1
    for (int it = 0; it < NIT; it++) {
        CP_WAIT0();
        __syncthreads();
        if (it + 1 < NIT) { load_stage((it + 1) & 1, (it + 1) * 32); CP_COMMIT(); }

        char* tA = sm + (it & 1) * ST2_BYTES;
        char* tB = tA + 32 * SKX * 2;
#pragma unroll
        for (int ks = 0; ks < 2; ks++) {
            int kk = ks * 16;
            uint32_t af[4][4];
#pragma unroll
            for (int mt = 0; mt < 4; mt++) {
                // x4.trans from [k][m]: m0=(k0-7,m0) m1=(k0-7,m8) m2=(k8-15,m0) m3=(k8-15,m8)
                int krow = kk + (lane & 7) + ((lane >> 4) & 1) * 8;
                int mcol = wm + mt * 16 + ((lane >> 3) & 1) * 8;
                ldsm_x4t(af[mt], smem_u32(tA + (krow * SKX + mcol) * 2));
            }
            uint32_t bfr[2][4];
#pragma unroll
            for (int nh = 0; nh < 2; nh++) {
                int krow = kk + (lane & 7) + ((lane >> 3) & 1) * 8;
                int ncol = wn + nh * 16 + ((lane >> 4) & 1) * 8;
                ldsm_x4t(bfr[nh], smem_u32(tB + (krow * SKX + ncol) * 2));
            }
#pragma unroll
            for (int mt = 0; mt < 4; mt++)
#pragma unroll
                for (int nt = 0; nt < 4; nt++)
                    mma16816(acc[mt][nt], af[mt], bfr[nt >> 1][(nt & 1) * 2],
                             bfr[nt >> 1][(nt & 1) * 2 + 1]);
        }
    }

    // epilogue: out = W - scale * acc
    const int tq = lane >> 2, tr = lane & 3;
#pragma unroll
    for (int mt = 0; mt < 4; mt++) {
#pragma unroll
        for (int nt = 0; nt < 4; nt++) {
            int row0 = i0 + wm + mt * 16 + tq;
            int col = j0 + wn + nt * 8 + tr * 2;
            float2 w0 = *(const float2*)&Wmat[(size_t)row0 * D + col];
            float2 w1 = *(const float2*)&Wmat[(size_t)(row0 + 8) * D + col];
            float2 o0, o1;
            o0.x = w0.x - scale * acc[mt][nt][0];
            o0.y = w0.y - scale * acc[mt][nt][1];
            o1.x = w1.x - scale * acc[mt][nt][2];
            o1.y = w1.y - scale * acc[mt][nt][3];
            *(float2*)&Out[(size_t)row0 * D + col] = o0;
            *(float2*)&Out[(size_t)(row0 + 8) * D + col] = o1;
        }
    }
}

// ---------------------------------------------------------------------------
// launch
// ---------------------------------------------------------------------------
extern "C" void kernel_launch(void* const* d_in, const int* in_sizes, int n_in,
                              void* d_out, int out_size)
{
    const float* Wmat = (const float*)d_in[0];
    const float* Kmat = (const float*)d_in[1];
    const float* Vmat = (const float*)d_in[2];
    float* Out = (float*)d_out;

    __nv_bfloat16 *Kb, *Wb, *P;
    cudaGetSymbolAddress((void**)&Kb, g_Kb);
    cudaGetSymbolAddress((void**)&Wb, g_Wb);
    cudaGetSymbolAddress((void**)&P, g_P);

    const float scale = 2.0f * 0.1f / ((float)CTX * (float)D);

    const int S1 = 2 * ST1_BYTES;  // 37888
    const int S2 = 2 * ST2_BYTES;  // 34816
    cudaFuncSetAttribute(gemm1_mma, cudaFuncAttributeMaxDynamicSharedMemorySize, S1);
    cudaFuncSetAttribute(gemm2_mma, cudaFuncAttributeMaxDynamicSharedMemorySize, S2);

    convert_kernel<<<(CTX * D) / (256 * 8), 256>>>((const float4*)Kmat, (__nv_bfloat162*)Kb);
    convert_kernel<<<(D * (size_t)D) / (256 * 8), 256>>>((const float4*)Wmat, (__nv_bfloat162*)Wb);

    gemm1_mma<<<dim3(D / 128, CTX / 128), 256, S1>>>(Kb, Wb, Vmat, P);
    gemm2_mma<<<dim3(D / 128, D / 128), 256, S2>>>(Kb, P, Wmat, Out, scale);
}

// round 8
// speedup vs baseline: 6.2231x; 1.1517x over previous
#include <cuda_runtime.h>
#include <cuda_bf16.h>
#include <cstdint>

// out = W - c * K^T (K W - V),  c = 2*0.1/(CTX*D)
// W: (4096,4096) f32, K: (512,4096) f32, V: (512,4096) f32
#define D 4096
#define CTX 512
#define SPLITK 4

// scratch (device globals -- no allocation allowed)
__device__ __align__(16) __nv_bfloat16 g_Kb[CTX * D];        // bf16 K          (4 MB)
__device__ __align__(16) __nv_bfloat16 g_Wb[(size_t)D * D];  // bf16 W          (32 MB)
__device__ __align__(16) __nv_bfloat16 g_P[CTX * D];         // bf16 (KW-V)     (4 MB)
__device__ __align__(16) float g_Pf[(size_t)SPLITK * CTX * D]; // split-K parts (32 MB)

// ---------------------------------------------------------------------------
// helpers (baseline PTX only -- harness targets sm_103 without 'a')
// ---------------------------------------------------------------------------
__device__ __forceinline__ uint32_t smem_u32(const void* p) {
    uint32_t a;
    asm("{ .reg .u64 t; cvta.to.shared.u64 t, %1; cvt.u32.u64 %0, t; }" : "=r"(a) : "l"(p));
    return a;
}
#define CP16(s, g)   asm volatile("cp.async.cg.shared.global [%0], [%1], 16;" :: "r"(s), "l"(g))
#define CP_COMMIT()  asm volatile("cp.async.commit_group;" ::: "memory")
#define CP_WAIT0()   asm volatile("cp.async.wait_group 0;" ::: "memory")
#define CP_WAIT1()   asm volatile("cp.async.wait_group 1;" ::: "memory")

__device__ __forceinline__ void ldsm_x4(uint32_t (&r)[4], uint32_t a) {
    asm volatile("ldmatrix.sync.aligned.m8n8.x4.shared.b16 {%0,%1,%2,%3}, [%4];"
                 : "=r"(r[0]), "=r"(r[1]), "=r"(r[2]), "=r"(r[3]) : "r"(a));
}
__device__ __forceinline__ void ldsm_x4t(uint32_t (&r)[4], uint32_t a) {
    asm volatile("ldmatrix.sync.aligned.m8n8.x4.trans.shared.b16 {%0,%1,%2,%3}, [%4];"
                 : "=r"(r[0]), "=r"(r[1]), "=r"(r[2]), "=r"(r[3]) : "r"(a));
}
__device__ __forceinline__ void mma16816(float (&d)[4], const uint32_t (&a)[4],
                                         uint32_t b0, uint32_t b1) {
    asm volatile("mma.sync.aligned.m16n8k16.row.col.f32.bf16.bf16.f32 "
                 "{%0,%1,%2,%3}, {%4,%5,%6,%7}, {%8,%9}, {%0,%1,%2,%3};"
                 : "+f"(d[0]), "+f"(d[1]), "+f"(d[2]), "+f"(d[3])
                 : "r"(a[0]), "r"(a[1]), "r"(a[2]), "r"(a[3]), "r"(b0), "r"(b1));
}

// ---------------------------------------------------------------------------
// prep: f32 -> bf16 (8 elems/thread)
// ---------------------------------------------------------------------------
__global__ void convert_kernel(const float4* __restrict__ src, __nv_bfloat162* __restrict__ dst) {
    int i = blockIdx.x * blockDim.x + threadIdx.x;
    float4 a = src[2 * i], b = src[2 * i + 1];
    dst[4 * i + 0] = __float22bfloat162_rn(make_float2(a.x, a.y));
    dst[4 * i + 1] = __float22bfloat162_rn(make_float2(a.z, a.w));
    dst[4 * i + 2] = __float22bfloat162_rn(make_float2(b.x, b.y));
    dst[4 * i + 3] = __float22bfloat162_rn(make_float2(b.z, b.w));
}

// reduce split-K partials, subtract V, emit bf16 P
__global__ void reduce_p_kernel(const float4* __restrict__ Pf, const float4* __restrict__ V,
                                __nv_bfloat162* __restrict__ P) {
    const int SL = CTX * D / 4;  // float4 per slice
    int i = blockIdx.x * blockDim.x + threadIdx.x;
    float4 s0 = Pf[i], s1 = Pf[i + SL], s2 = Pf[i + 2 * SL], s3 = Pf[i + 3 * SL];
    float4 v = V[i];
    float4 r;
    r.x = (s0.x + s1.x) + (s2.x + s3.x) - v.x;
    r.y = (s0.y + s1.y) + (s2.y + s3.y) - v.y;
    r.z = (s0.z + s1.z) + (s2.z + s3.z) - v.z;
    r.w = (s0.w + s1.w) + (s2.w + s3.w) - v.w;
    P[2 * i + 0] = __float22bfloat162_rn(make_float2(r.x, r.y));
    P[2 * i + 1] = __float22bfloat162_rn(make_float2(r.z, r.w));
}

// smem strides (elements): A1 tile [128 m][32 k] pad->40 ; [k][x] tiles [32][128] pad->136
#define SA1 40
#define SKX 136
#define ST1_BYTES (128 * SA1 * 2 + 32 * SKX * 2)   // 18944
#define ST2_BYTES (2 * 32 * SKX * 2)               // 17408
#define NSTAGE 3

// ---------------------------------------------------------------------------
// GEMM1 (split-K): Pf[z][c][n] = sum_{k in slice z} K[c][k] W[k][n]
// A = Kb [m][k] (non-trans), B = Wb [k][n] (trans).  grid (32,4,4), 256 thr
// ---------------------------------------------------------------------------
__global__ __launch_bounds__(256) void gemm1_mma_sk(
    const __nv_bfloat16* __restrict__ Kb, const __nv_bfloat16* __restrict__ Wb,
    float* __restrict__ Pf)
{
    extern __shared__ __align__(16) char sm[];
    const int tid = threadIdx.x, lane = tid & 31, wid = tid >> 5;
    const int j0 = blockIdx.x * 128, c0 = blockIdx.y * 128;
    const int kbase = blockIdx.z * (D / SPLITK);
    const int wm = (wid >> 2) * 64, wn = (wid & 3) * 32;

    float acc[4][4][4];
#pragma unroll
    for (int mt = 0; mt < 4; mt++)
#pragma unroll
        for (int nt = 0; nt < 4; nt++)
#pragma unroll
            for (int e = 0; e < 4; e++) acc[mt][nt][e] = 0.f;

    auto load_stage = [&](int stage, int k0) {
        char* tA = sm + stage * ST1_BYTES;
        char* tB = tA + 128 * SA1 * 2;
#pragma unroll
        for (int i = 0; i < 2; i++) {
            int c = tid + i * 256;
            int m = c >> 2, part = c & 3;
            CP16(smem_u32(tA + (m * SA1 + part * 8) * 2),
                 Kb + (size_t)(c0 + m) * D + k0 + part * 8);
        }
#pragma unroll
        for (int i = 0; i < 2; i++) {
            int c = tid + i * 256;
            int kk = c >> 4, part = c & 15;
            CP16(smem_u32(tB + (kk * SKX + part * 8) * 2),
                 Wb + (size_t)(k0 + kk) * D + j0 + part * 8);
        }
    };

    // hoisted smem fragment addresses (stage 0, ks 0)
    const uint32_t smb = smem_u32(sm);
    uint32_t aA[4], aB[2];
#pragma unroll
    for (int mt = 0; mt < 4; mt++) {
        int m = wm + mt * 16 + (lane & 15);
        int cc = (lane >> 4) << 3;
        aA[mt] = smb + (m * SA1 + cc) * 2;
    }
#pragma unroll
    for (int nh = 0; nh < 2; nh++) {
        int krow = (lane & 7) + ((lane >> 3) & 1) * 8;
        int ncol = wn + nh * 16 + ((lane >> 4) & 1) * 8;
        aB[nh] = smb + 128 * SA1 * 2 + (krow * SKX + ncol) * 2;
    }

    const int NIT = (D / SPLITK) / 32;  // 32
    load_stage(0, kbase);
    CP_COMMIT();
    load_stage(1, kbase + 32);
    CP_COMMIT();

#pragma unroll 1
    for (int it = 0; it < NIT; it++) {
        if (it < NIT - 1) CP_WAIT1(); else CP_WAIT0();
        __syncthreads();
        if (it + 2 < NIT) { load_stage((it + 2) % NSTAGE, kbase + (it + 2) * 32); CP_COMMIT(); }

        const uint32_t sb = (uint32_t)((it % NSTAGE) * ST1_BYTES);
#pragma unroll
        for (int ks = 0; ks < 2; ks++) {
            const uint32_t oA = sb + ks * 32;               // +16 k elems * 2B
            const uint32_t oB = sb + ks * 16 * SKX * 2;     // +16 k rows
            uint32_t af[4][4];
#pragma unroll
            for (int mt = 0; mt < 4; mt++) ldsm_x4(af[mt], aA[mt] + oA);
            uint32_t bfr[2][4];
#pragma unroll
            for (int nh = 0; nh < 2; nh++) ldsm_x4t(bfr[nh], aB[nh] + oB);
#pragma unroll
            for (int mt = 0; mt < 4; mt++)
#pragma unroll
                for (int nt = 0; nt < 4; nt++)
                    mma16816(acc[mt][nt], af[mt], bfr[nt >> 1][(nt & 1) * 2],
                             bfr[nt >> 1][(nt & 1) * 2 + 1]);
        }
        __syncthreads();
    }

    // epilogue: f32 partial stores
    const int tq = lane >> 2, tr = lane & 3;
    float* PfZ = Pf + (size_t)blockIdx.z * CTX * D;
#pragma unroll
    for (int mt = 0; mt < 4; mt++) {
#pragma unroll
        for (int nt = 0; nt < 4; nt++) {
            int row0 = c0 + wm + mt * 16 + tq;
            int col = j0 + wn + nt * 8 + tr * 2;
            *(float2*)&PfZ[(size_t)row0 * D + col] = make_float2(acc[mt][nt][0], acc[mt][nt][1]);
            *(float2*)&PfZ[(size_t)(row0 + 8) * D + col] = make_float2(acc[mt][nt][2], acc[mt][nt][3]);
        }
    }
}

// ---------------------------------------------------------------------------
// GEMM2: out[i][j] = W[i][j] - scale * sum_c K[c][i] P[c][j]
// A = Kb [k][m] (trans), B = P [k][n] (trans).  grid (32,32), 256 thr
// ---------------------------------------------------------------------------
__global__ __launch_bounds__(256) void gemm2_mma(
    const __nv_bfloat16* __restrict__ Kb, const __nv_bfloat16* __restrict__ P,
    const float* __restrict__ Wmat, float* __restrict__ Out, float scale)
{
    extern __shared__ __align__(16) char sm[];
    const int tid = threadIdx.x, lane = tid & 31, wid = tid >> 5;
    const int j0 = blockIdx.x * 128, i0 = blockIdx.y * 128;
    const int wm = (wid >> 2) * 64, wn = (wid & 3) * 32;

    float acc[4][4][4];
#pragma unroll
    for (int mt = 0; mt < 4; mt++)
#pragma unroll
        for (int nt = 0; nt < 4; nt++)
#pragma unroll
            for (int e = 0; e < 4; e++) acc[mt][nt][e] = 0.f;

    auto load_stage = [&](int stage, int k0) {
        char* tA = sm + stage * ST2_BYTES;
        char* tB = tA + 32 * SKX * 2;
#pragma unroll
        for (int i = 0; i < 2; i++) {
            int c = tid + i * 256;
            int kk = c >> 4, part = c & 15;
            CP16(smem_u32(tA + (kk * SKX + part * 8) * 2),
                 Kb + (size_t)(k0 + kk) * D + i0 + part * 8);
        }
#pragma unroll
        for (int i = 0; i < 2; i++) {
            int c = tid + i * 256;
            int kk = c >> 4, part = c & 15;
            CP16(smem_u32(tB + (kk * SKX + part * 8) * 2),
                 P + (size_t)(k0 + kk) * D + j0 + part * 8);
        }
    };

    // hoisted fragment addresses (stage 0, ks 0); both operands use trans loads
    const uint32_t smb = smem_u32(sm);
    const int krow0 = (lane & 7) + ((lane >> 3) & 1) * 8;
    uint32_t aA[4], aB[2];
#pragma unroll
    for (int mt = 0; mt < 4; mt++) {
        int mcol = wm + mt * 16 + ((lane >> 3) & 1) * 8;
        // NOTE: A-frag trans layout uses krow = (lane&7) + ((lane>>4)&1)*8
        int krA = (lane & 7) + ((lane >> 4) & 1) * 8;
        aA[mt] = smb + (krA * SKX + mcol) * 2;
    }
#pragma unroll
    for (int nh = 0; nh < 2; nh++) {
        int ncol = wn + nh * 16 + ((lane >> 4) & 1) * 8;
        aB[nh] = smb + 32 * SKX * 2 + (krow0 * SKX + ncol) * 2;
    }

    const int NIT = CTX / 32;  // 16
    load_stage(0, 0);
    CP_COMMIT();
    load_stage(1, 32);
    CP_COMMIT();

#pragma unroll 1
    for (int it = 0; it < NIT; it++) {
        if (it < NIT - 1) CP_WAIT1(); else CP_WAIT0();
        __syncthreads();
        if (it + 2 < NIT) { load_stage((it + 2) % NSTAGE, (it + 2) * 32); CP_COMMIT(); }

        const uint32_t sb = (uint32_t)((it % NSTAGE) * ST2_BYTES);
#pragma unroll
        for (int ks = 0; ks < 2; ks++) {
            const uint32_t oK = sb + ks * 16 * SKX * 2;
            uint32_t af[4][4];
#pragma unroll
            for (int mt = 0; mt < 4; mt++) ldsm_x4t(af[mt], aA[mt] + oK);
            uint32_t bfr[2][4];
#pragma unroll
            for (int nh = 0; nh < 2; nh++) ldsm_x4t(bfr[nh], aB[nh] + oK);
#pragma unroll
            for (int mt = 0; mt < 4; mt++)
#pragma unroll
                for (int nt = 0; nt < 4; nt++)
                    mma16816(acc[mt][nt], af[mt], bfr[nt >> 1][(nt & 1) * 2],
                             bfr[nt >> 1][(nt & 1) * 2 + 1]);
        }
        __syncthreads();
    }

    // epilogue: out = W - scale * acc
    const int tq = lane >> 2, tr = lane & 3;
#pragma unroll
    for (int mt = 0; mt < 4; mt++) {
#pragma unroll
        for (int nt = 0; nt < 4; nt++) {
            int row0 = i0 + wm + mt * 16 + tq;
            int col = j0 + wn + nt * 8 + tr * 2;
            float2 w0 = *(const float2*)&Wmat[(size_t)row0 * D + col];
            float2 w1 = *(const float2*)&Wmat[(size_t)(row0 + 8) * D + col];
            float2 o0, o1;
            o0.x = w0.x - scale * acc[mt][nt][0];
            o0.y = w0.y - scale * acc[mt][nt][1];
            o1.x = w1.x - scale * acc[mt][nt][2];
            o1.y = w1.y - scale * acc[mt][nt][3];
            *(float2*)&Out[(size_t)row0 * D + col] = o0;
            *(float2*)&Out[(size_t)(row0 + 8) * D + col] = o1;
        }
    }
}

// ---------------------------------------------------------------------------
// launch
// ---------------------------------------------------------------------------
extern "C" void kernel_launch(void* const* d_in, const int* in_sizes, int n_in,
                              void* d_out, int out_size)
{
    const float* Wmat = (const float*)d_in[0];
    const float* Kmat = (const float*)d_in[1];
    const float* Vmat = (const float*)d_in[2];
    float* Out = (float*)d_out;

    __nv_bfloat16 *Kb, *Wb, *P;
    float* Pf;
    cudaGetSymbolAddress((void**)&Kb, g_Kb);
    cudaGetSymbolAddress((void**)&Wb, g_Wb);
    cudaGetSymbolAddress((void**)&P, g_P);
    cudaGetSymbolAddress((void**)&Pf, g_Pf);

    const float scale = 2.0f * 0.1f / ((float)CTX * (float)D);

    const int S1 = NSTAGE * ST1_BYTES;  // 56832
    const int S2 = NSTAGE * ST2_BYTES;  // 52224
    cudaFuncSetAttribute(gemm1_mma_sk, cudaFuncAttributeMaxDynamicSharedMemorySize, S1);
    cudaFuncSetAttribute(gemm2_mma, cudaFuncAttributeMaxDynamicSharedMemorySize, S2);

    convert_kernel<<<(CTX * D) / (256 * 8), 256>>>((const float4*)Kmat, (__nv_bfloat162*)Kb);
    convert_kernel<<<(D * (size_t)D) / (256 * 8), 256>>>((const float4*)Wmat, (__nv_bfloat162*)Wb);

    gemm1_mma_sk<<<dim3(D / 128, CTX / 128, SPLITK), 256, S1>>>(Kb, Wb, Pf);
    reduce_p_kernel<<<(CTX * D / 4) / 256, 256>>>((const float4*)Pf, (const float4*)Vmat,
                                                  (__nv_bfloat162*)P);
    gemm2_mma<<<dim3(D / 128, D / 128), 256, S2>>>(Kb, P, Wmat, Out, scale);
}

// round 10
// speedup vs baseline: 6.3599x; 1.0220x over previous
#include <cuda_runtime.h>
#include <cuda_bf16.h>
#include <cstdint>

// out = W - c * K^T (K W - V),  c = 2*0.1/(CTX*D)
// W: (4096,4096) f32, K: (512,4096) f32, V: (512,4096) f32
#define D 4096
#define CTX 512

// scratch (device globals -- no allocation allowed)
__device__ __align__(16) __nv_bfloat16 g_Kb[CTX * D];        // bf16 K      (4 MB)
__device__ __align__(16) __nv_bfloat16 g_Wb[(size_t)D * D];  // bf16 W      (32 MB)
__device__ __align__(16) __nv_bfloat16 g_P[CTX * D];         // bf16 (KW-V) (4 MB)

// ---------------------------------------------------------------------------
// helpers (baseline PTX only -- harness targets sm_103 without 'a')
// ---------------------------------------------------------------------------
__device__ __forceinline__ uint32_t smem_u32(const void* p) {
    uint32_t a;
    asm("{ .reg .u64 t; cvta.to.shared.u64 t, %1; cvt.u32.u64 %0, t; }" : "=r"(a) : "l"(p));
    return a;
}
#define CP16(s, g)   asm volatile("cp.async.cg.shared.global [%0], [%1], 16;" :: "r"(s), "l"(g))
#define CP_COMMIT()  asm volatile("cp.async.commit_group;" ::: "memory")
#define CP_WAIT0()   asm volatile("cp.async.wait_group 0;" ::: "memory")
#define CP_WAIT2()   asm volatile("cp.async.wait_group 2;" ::: "memory")

__device__ __forceinline__ void ldsm_x4(uint32_t (&r)[4], uint32_t a) {
    asm volatile("ldmatrix.sync.aligned.m8n8.x4.shared.b16 {%0,%1,%2,%3}, [%4];"
                 : "=r"(r[0]), "=r"(r[1]), "=r"(r[2]), "=r"(r[3]) : "r"(a));
}
__device__ __forceinline__ void ldsm_x4t(uint32_t (&r)[4], uint32_t a) {
    asm volatile("ldmatrix.sync.aligned.m8n8.x4.trans.shared.b16 {%0,%1,%2,%3}, [%4];"
                 : "=r"(r[0]), "=r"(r[1]), "=r"(r[2]), "=r"(r[3]) : "r"(a));
}
__device__ __forceinline__ void mma16816(float (&d)[4], const uint32_t (&a)[4],
                                         uint32_t b0, uint32_t b1) {
    asm volatile("mma.sync.aligned.m16n8k16.row.col.f32.bf16.bf16.f32 "
                 "{%0,%1,%2,%3}, {%4,%5,%6,%7}, {%8,%9}, {%0,%1,%2,%3};"
                 : "+f"(d[0]), "+f"(d[1]), "+f"(d[2]), "+f"(d[3])
                 : "r"(a[0]), "r"(a[1]), "r"(a[2]), "r"(a[3]), "r"(b0), "r"(b1));
}

// ---------------------------------------------------------------------------
// prep: f32 -> bf16 (8 elems/thread)
// ---------------------------------------------------------------------------
__global__ void convert_kernel(const float4* __restrict__ src, __nv_bfloat162* __restrict__ dst) {
    int i = blockIdx.x * blockDim.x + threadIdx.x;
    float4 a = src[2 * i], b = src[2 * i + 1];
    dst[4 * i + 0] = __float22bfloat162_rn(make_float2(a.x, a.y));
    dst[4 * i + 1] = __float22bfloat162_rn(make_float2(a.z, a.w));
    dst[4 * i + 2] = __float22bfloat162_rn(make_float2(b.x, b.y));
    dst[4 * i + 3] = __float22bfloat162_rn(make_float2(b.z, b.w));
}

// smem strides (elems): A1 tile [64 m][32 k] pad->40 ; [k][x] tiles [32][128] pad->136
#define SA1 40
#define SKX 136
#define ST1_BYTES (64 * SA1 * 2 + 32 * SKX * 2)    // 5120 + 8704 = 13824
#define ST2_BYTES (2 * 32 * SKX * 2)               // 17408
#define NSTAGE 4

// ---------------------------------------------------------------------------
// GEMM1: P[c][n] = bf16( sum_k K[c][k] W[k][n] - V[c][n] )
// A = Kb [m][k] (non-trans), B = Wb [k][n] (trans).
// M-tile 64 -> grid (32, 8) = 256 CTAs, 256 thr, warp tile 32x32
// ---------------------------------------------------------------------------
__global__ __launch_bounds__(256) void gemm1_mma(
    const __nv_bfloat16* __restrict__ Kb, const __nv_bfloat16* __restrict__ Wb,
    const float* __restrict__ Vmat, __nv_bfloat16* __restrict__ P)
{
    extern __shared__ __align__(16) char sm[];
    const int tid = threadIdx.x, lane = tid & 31, wid = tid >> 5;
    const int j0 = blockIdx.x * 128, c0 = blockIdx.y * 64;
    const int wm = (wid >> 2) * 32, wn = (wid & 3) * 32;

    float acc[2][4][4];
#pragma unroll
    for (int mt = 0; mt < 2; mt++)
#pragma unroll
        for (int nt = 0; nt < 4; nt++)
#pragma unroll
            for (int e = 0; e < 4; e++) acc[mt][nt][e] = 0.f;

    auto load_stage = [&](int stage, int k0) {
        char* tA = sm + stage * ST1_BYTES;
        char* tB = tA + 64 * SA1 * 2;
        {   // A: 64 rows x 4 chunks = 256 chunks, 1 per thread
            int m = tid >> 2, part = tid & 3;
            CP16(smem_u32(tA + (m * SA1 + part * 8) * 2),
                 Kb + (size_t)(c0 + m) * D + k0 + part * 8);
        }
        {   // B: 32 rows x 16 chunks = 512 chunks, 2 per thread
#pragma unroll
            for (int i = 0; i < 2; i++) {
                int c = tid + i * 256;
                int kk = c >> 4, part = c & 15;
                CP16(smem_u32(tB + (kk * SKX + part * 8) * 2),
                     Wb + (size_t)(k0 + kk) * D + j0 + part * 8);
            }
        }
    };

    // hoisted fragment addresses (stage 0, ks 0)
    const uint32_t smb = smem_u32(sm);
    uint32_t aA[2], aB[2];
#pragma unroll
    for (int mt = 0; mt < 2; mt++) {
        int m = wm + mt * 16 + (lane & 15);
        int cc = (lane >> 4) << 3;
        aA[mt] = smb + (m * SA1 + cc) * 2;
    }
#pragma unroll
    for (int nh = 0; nh < 2; nh++) {
        int krow = (lane & 7) + ((lane >> 3) & 1) * 8;
        int ncol = wn + nh * 16 + ((lane >> 4) & 1) * 8;
        aB[nh] = smb + 64 * SA1 * 2 + (krow * SKX + ncol) * 2;
    }

    const int NIT = D / 32;  // 128
    load_stage(0, 0); CP_COMMIT();
    load_stage(1, 32); CP_COMMIT();
    load_stage(2, 64); CP_COMMIT();

#pragma unroll 1
    for (int it = 0; it < NIT; it++) {
        if (it < NIT - 2) CP_WAIT2(); else CP_WAIT0();
        __syncthreads();
        if (it + 3 < NIT) { load_stage((it + 3) & (NSTAGE - 1), (it + 3) * 32); CP_COMMIT(); }

        const uint32_t sb = (uint32_t)((it & (NSTAGE - 1)) * ST1_BYTES);
#pragma unroll
        for (int ks = 0; ks < 2; ks++) {
            const uint32_t oA = sb + ks * 32;             // +16 k elems * 2B
            const uint32_t oB = sb + ks * 16 * SKX * 2;   // +16 k rows
            uint32_t af[2][4];
#pragma unroll
            for (int mt = 0; mt < 2; mt++) ldsm_x4(af[mt], aA[mt] + oA);
            uint32_t bfr[2][4];
#pragma unroll
            for (int nh = 0; nh < 2; nh++) ldsm_x4t(bfr[nh], aB[nh] + oB);
#pragma unroll
            for (int mt = 0; mt < 2; mt++)
#pragma unroll
                for (int nt = 0; nt < 4; nt++)
                    mma16816(acc[mt][nt], af[mt], bfr[nt >> 1][(nt & 1) * 2],
                             bfr[nt >> 1][(nt & 1) * 2 + 1]);
        }
    }

    // epilogue: P = bf16(acc - V)
    const int tq = lane >> 2, tr = lane & 3;
#pragma unroll
    for (int mt = 0; mt < 2; mt++) {
#pragma unroll
        for (int nt = 0; nt < 4; nt++) {
            int row0 = c0 + wm + mt * 16 + tq;
            int col = j0 + wn + nt * 8 + tr * 2;
            float2 v0 = *(const float2*)&Vmat[(size_t)row0 * D + col];
            float2 v1 = *(const float2*)&Vmat[(size_t)(row0 + 8) * D + col];
            __nv_bfloat162 p0, p1;
            p0.x = __float2bfloat16(acc[mt][nt][0] - v0.x);
            p0.y = __float2bfloat16(acc[mt][nt][1] - v0.y);
            p1.x = __float2bfloat16(acc[mt][nt][2] - v1.x);
            p1.y = __float2bfloat16(acc[mt][nt][3] - v1.y);
            *(__nv_bfloat162*)&P[(size_t)row0 * D + col] = p0;
            *(__nv_bfloat162*)&P[(size_t)(row0 + 8) * D + col] = p1;
        }
    }
}

// ---------------------------------------------------------------------------
// GEMM2: out[i][j] = W[i][j] - scale * sum_c K[c][i] P[c][j]
// A = Kb [k][m] (trans), B = P [k][n] (trans).  grid (32,32), 256 thr
// ---------------------------------------------------------------------------
__global__ __launch_bounds__(256) void gemm2_mma(
    const __nv_bfloat16* __restrict__ Kb, const __nv_bfloat16* __restrict__ P,
    const float* __restrict__ Wmat, float* __restrict__ Out, float scale)
{
    extern __shared__ __align__(16) char sm[];
    const int tid = threadIdx.x, lane = tid & 31, wid = tid >> 5;
    const int j0 = blockIdx.x * 128, i0 = blockIdx.y * 128;
    const int wm = (wid >> 2) * 64, wn = (wid & 3) * 32;

    float acc[4][4][4];
#pragma unroll
    for (int mt = 0; mt < 4; mt++)
#pragma unroll
        for (int nt = 0; nt < 4; nt++)
#pragma unroll
            for (int e = 0; e < 4; e++) acc[mt][nt][e] = 0.f;

    auto load_stage = [&](int stage, int k0) {
        char* tA = sm + stage * ST2_BYTES;
        char* tB = tA + 32 * SKX * 2;
#pragma unroll
        for (int i = 0; i < 2; i++) {
            int c = tid + i * 256;
            int kk = c >> 4, part = c & 15;
            CP16(smem_u32(tA + (kk * SKX + part * 8) * 2),
                 Kb + (size_t)(k0 + kk) * D + i0 + part * 8);
        }
#pragma unroll
        for (int i = 0; i < 2; i++) {
            int c = tid + i * 256;
            int kk = c >> 4, part = c & 15;
            CP16(smem_u32(tB + (kk * SKX + part * 8) * 2),
                 P + (size_t)(k0 + kk) * D + j0 + part * 8);
        }
    };

    // hoisted fragment addresses (stage 0, ks 0); both operands trans
    const uint32_t smb = smem_u32(sm);
    const int krow0 = (lane & 7) + ((lane >> 3) & 1) * 8;
    uint32_t aA[4], aB[2];
#pragma unroll
    for (int mt = 0; mt < 4; mt++) {
        int mcol = wm + mt * 16 + ((lane >> 3) & 1) * 8;
        int krA = (lane & 7) + ((lane >> 4) & 1) * 8;
        aA[mt] = smb + (krA * SKX + mcol) * 2;
    }
#pragma unroll
    for (int nh = 0; nh < 2; nh++) {
        int ncol = wn + nh * 16 + ((lane >> 4) & 1) * 8;
        aB[nh] = smb + 32 * SKX * 2 + (krow0 * SKX + ncol) * 2;
    }

    const int NIT = CTX / 32;  // 16
    load_stage(0, 0); CP_COMMIT();
    load_stage(1, 32); CP_COMMIT();
    load_stage(2, 64); CP_COMMIT();

#pragma unroll 1
    for (int it = 0; it < NIT; it++) {
        if (it < NIT - 2) CP_WAIT2(); else CP_WAIT0();
        __syncthreads();
        if (it + 3 < NIT) { load_stage((it + 3) & (NSTAGE - 1), (it + 3) * 32); CP_COMMIT(); }

        const uint32_t sb = (uint32_t)((it & (NSTAGE - 1)) * ST2_BYTES);
#pragma unroll
        for (int ks = 0; ks < 2; ks++) {
            const uint32_t oK = sb + ks * 16 * SKX * 2;
            uint32_t af[4][4];
#pragma unroll
            for (int mt = 0; mt < 4; mt++) ldsm_x4t(af[mt], aA[mt] + oK);
            uint32_t bfr[2][4];
#pragma unroll
            for (int nh = 0; nh < 2; nh++) ldsm_x4t(bfr[nh], aB[nh] + oK);
#pragma unroll
            for (int mt = 0; mt < 4; mt++)
#pragma unroll
                for (int nt = 0; nt < 4; nt++)
                    mma16816(acc[mt][nt], af[mt], bfr[nt >> 1][(nt & 1) * 2],
                             bfr[nt >> 1][(nt & 1) * 2 + 1]);
        }
    }

    // epilogue: out = W - scale * acc
    const int tq = lane >> 2, tr = lane & 3;
#pragma unroll
    for (int mt = 0; mt < 4; mt++) {
#pragma unroll
        for (int nt = 0; nt < 4; nt++) {
            int row0 = i0 + wm + mt * 16 + tq;
            int col = j0 + wn + nt * 8 + tr * 2;
            float2 w0 = *(const float2*)&Wmat[(size_t)row0 * D + col];
            float2 w1 = *(const float2*)&Wmat[(size_t)(row0 + 8) * D + col];
            float2 o0, o1;
            o0.x = w0.x - scale * acc[mt][nt][0];
            o0.y = w0.y - scale * acc[mt][nt][1];
            o1.x = w1.x - scale * acc[mt][nt][2];
            o1.y = w1.y - scale * acc[mt][nt][3];
            *(float2*)&Out[(size_t)row0 * D + col] = o0;
            *(float2*)&Out[(size_t)(row0 + 8) * D + col] = o1;
        }
    }
}

// ---------------------------------------------------------------------------
// launch
// ---------------------------------------------------------------------------
extern "C" void kernel_launch(void* const* d_in, const int* in_sizes, int n_in,
                              void* d_out, int out_size)
{
    const float* Wmat = (const float*)d_in[0];
    const float* Kmat = (const float*)d_in[1];
    const float* Vmat = (const float*)d_in[2];
    float* Out = (float*)d_out;

    __nv_bfloat16 *Kb, *Wb, *P;
    cudaGetSymbolAddress((void**)&Kb, g_Kb);
    cudaGetSymbolAddress((void**)&Wb, g_Wb);
    cudaGetSymbolAddress((void**)&P, g_P);

    const float scale = 2.0f * 0.1f / ((float)CTX * (float)D);

    const int S1 = NSTAGE * ST1_BYTES;  // 55296
    const int S2 = NSTAGE * ST2_BYTES;  // 69632
    cudaFuncSetAttribute(gemm1_mma, cudaFuncAttributeMaxDynamicSharedMemorySize, S1);
    cudaFuncSetAttribute(gemm2_mma, cudaFuncAttributeMaxDynamicSharedMemorySize, S2);

    convert_kernel<<<(CTX * D) / (256 * 8), 256>>>((const float4*)Kmat, (__nv_bfloat162*)Kb);
    convert_kernel<<<(D * (size_t)D) / (256 * 8), 256>>>((const float4*)Wmat, (__nv_bfloat162*)Wb);

    gemm1_mma<<<dim3(D / 128, CTX / 64), 256, S1>>>(Kb, Wb, Vmat, P);
    gemm2_mma<<<dim3(D / 128, D / 128), 256, S2>>>(Kb, P, Wmat, Out, scale);
}

// round 11
// speedup vs baseline: 7.0552x; 1.1093x over previous
#include <cuda_runtime.h>
#include <cuda_bf16.h>
#include <cstdint>

// out = W - c * K^T (K W - V),  c = 2*0.1/(CTX*D)
// W: (4096,4096) f32, K: (512,4096) f32, V: (512,4096) f32
#define D 4096
#define CTX 512
#define SPLITK 2

// scratch (device globals -- no allocation allowed)
__device__ __align__(16) __nv_bfloat16 g_Kb[CTX * D];          // bf16 K      (4 MB)
__device__ __align__(16) __nv_bfloat16 g_Wb[(size_t)D * D];    // bf16 W      (32 MB)
__device__ __align__(16) __nv_bfloat16 g_P[CTX * D];           // bf16 (KW-V) (4 MB)
__device__ __align__(16) float g_Pf[(size_t)SPLITK * CTX * D]; // f32 partials(16 MB)

// ---------------------------------------------------------------------------
// helpers (baseline PTX only -- harness targets sm_103 without 'a')
// ---------------------------------------------------------------------------
__device__ __forceinline__ uint32_t smem_u32(const void* p) {
    uint32_t a;
    asm("{ .reg .u64 t; cvta.to.shared.u64 t, %1; cvt.u32.u64 %0, t; }" : "=r"(a) : "l"(p));
    return a;
}
#define CP16(s, g)   asm volatile("cp.async.cg.shared.global [%0], [%1], 16;" :: "r"(s), "l"(g))
#define CP_COMMIT()  asm volatile("cp.async.commit_group;" ::: "memory")
#define CP_WAIT0()   asm volatile("cp.async.wait_group 0;" ::: "memory")
#define CP_WAIT2()   asm volatile("cp.async.wait_group 2;" ::: "memory")

__device__ __forceinline__ void ldsm_x4(uint32_t (&r)[4], uint32_t a) {
    asm volatile("ldmatrix.sync.aligned.m8n8.x4.shared.b16 {%0,%1,%2,%3}, [%4];"
                 : "=r"(r[0]), "=r"(r[1]), "=r"(r[2]), "=r"(r[3]) : "r"(a));
}
__device__ __forceinline__ void ldsm_x4t(uint32_t (&r)[4], uint32_t a) {
    asm volatile("ldmatrix.sync.aligned.m8n8.x4.trans.shared.b16 {%0,%1,%2,%3}, [%4];"
                 : "=r"(r[0]), "=r"(r[1]), "=r"(r[2]), "=r"(r[3]) : "r"(a));
}
__device__ __forceinline__ void mma16816(float (&d)[4], const uint32_t (&a)[4],
                                         uint32_t b0, uint32_t b1) {
    asm volatile("mma.sync.aligned.m16n8k16.row.col.f32.bf16.bf16.f32 "
                 "{%0,%1,%2,%3}, {%4,%5,%6,%7}, {%8,%9}, {%0,%1,%2,%3};"
                 : "+f"(d[0]), "+f"(d[1]), "+f"(d[2]), "+f"(d[3])
                 : "r"(a[0]), "r"(a[1]), "r"(a[2]), "r"(a[3]), "r"(b0), "r"(b1));
}

// ---------------------------------------------------------------------------
// prep: f32 -> bf16 (8 elems/thread)
// ---------------------------------------------------------------------------
__global__ void convert_kernel(const float4* __restrict__ src, __nv_bfloat162* __restrict__ dst) {
    int i = blockIdx.x * blockDim.x + threadIdx.x;
    float4 a = src[2 * i], b = src[2 * i + 1];
    dst[4 * i + 0] = __float22bfloat162_rn(make_float2(a.x, a.y));
    dst[4 * i + 1] = __float22bfloat162_rn(make_float2(a.z, a.w));
    dst[4 * i + 2] = __float22bfloat162_rn(make_float2(b.x, b.y));
    dst[4 * i + 3] = __float22bfloat162_rn(make_float2(b.z, b.w));
}

// reduce 2 split-K partials, subtract V, emit bf16 P
__global__ void reduce_p_kernel(const float4* __restrict__ Pf, const float4* __restrict__ V,
                                __nv_bfloat162* __restrict__ P) {
    const int SL = CTX * D / 4;
    int i = blockIdx.x * blockDim.x + threadIdx.x;
    float4 s0 = Pf[i], s1 = Pf[i + SL];
    float4 v = V[i];
    float4 r;
    r.x = (s0.x + s1.x) - v.x;
    r.y = (s0.y + s1.y) - v.y;
    r.z = (s0.z + s1.z) - v.z;
    r.w = (s0.w + s1.w) - v.w;
    P[2 * i + 0] = __float22bfloat162_rn(make_float2(r.x, r.y));
    P[2 * i + 1] = __float22bfloat162_rn(make_float2(r.z, r.w));
}

// smem strides (elems): A1 tile [128 m][32 k] pad->40 ; [k][x] tiles [32][128] pad->136
#define SA1 40
#define SKX 136
#define ST1_BYTES (128 * SA1 * 2 + 32 * SKX * 2)   // 10240 + 8704 = 18944
#define ST2_BYTES (2 * 32 * SKX * 2)               // 17408
#define NSTAGE 4

// ---------------------------------------------------------------------------
// GEMM1 (split-K=2): Pf[z][c][n] = sum_{k in slice z} K[c][k] W[k][n]
// A = Kb [m][k] (non-trans), B = Wb [k][n] (trans).
// CTA 128x128, 128 thr, 4 warps 2x2, warp tile 64x64.  grid (32,4,2)
// ---------------------------------------------------------------------------
__global__ __launch_bounds__(128) void gemm1_mma_sk(
    const __nv_bfloat16* __restrict__ Kb, const __nv_bfloat16* __restrict__ Wb,
    float* __restrict__ Pf)
{
    extern __shared__ __align__(16) char sm[];
    const int tid = threadIdx.x, lane = tid & 31, wid = tid >> 5;
    const int j0 = blockIdx.x * 128, c0 = blockIdx.y * 128;
    const int kbase = blockIdx.z * (D / SPLITK);
    const int wm = (wid >> 1) * 64, wn = (wid & 1) * 64;

    float acc[4][8][4];
#pragma unroll
    for (int mt = 0; mt < 4; mt++)
#pragma unroll
        for (int nt = 0; nt < 8; nt++)
#pragma unroll
            for (int e = 0; e < 4; e++) acc[mt][nt][e] = 0.f;

    auto load_stage = [&](int stage, int k0) {
        char* tA = sm + stage * ST1_BYTES;
        char* tB = tA + 128 * SA1 * 2;
#pragma unroll
        for (int i = 0; i < 4; i++) {      // A: 128 rows x 4 chunks = 512, 4/thread
            int c = tid + i * 128;
            int m = c >> 2, part = c & 3;
            CP16(smem_u32(tA + (m * SA1 + part * 8) * 2),
                 Kb + (size_t)(c0 + m) * D + k0 + part * 8);
        }
#pragma unroll
        for (int i = 0; i < 4; i++) {      // B: 32 rows x 16 chunks = 512, 4/thread
            int c = tid + i * 128;
            int kk = c >> 4, part = c & 15;
            CP16(smem_u32(tB + (kk * SKX + part * 8) * 2),
                 Wb + (size_t)(k0 + kk) * D + j0 + part * 8);
        }
    };

    // hoisted fragment addresses (stage 0, ks 0)
    const uint32_t smb = smem_u32(sm);
    uint32_t aA[4], aB[4];
#pragma unroll
    for (int mt = 0; mt < 4; mt++) {
        int m = wm + mt * 16 + (lane & 15);
        int cc = (lane >> 4) << 3;
        aA[mt] = smb + (m * SA1 + cc) * 2;
    }
#pragma unroll
    for (int nh = 0; nh < 4; nh++) {
        int krow = (lane & 7) + ((lane >> 3) & 1) * 8;
        int ncol = wn + nh * 16 + ((lane >> 4) & 1) * 8;
        aB[nh] = smb + 128 * SA1 * 2 + (krow * SKX + ncol) * 2;
    }

    const int NIT = (D / SPLITK) / 32;  // 64
    load_stage(0, kbase); CP_COMMIT();
    load_stage(1, kbase + 32); CP_COMMIT();
    load_stage(2, kbase + 64); CP_COMMIT();

#pragma unroll 1
    for (int it = 0; it < NIT; it++) {
        if (it < NIT - 2) CP_WAIT2(); else CP_WAIT0();
        __syncthreads();
        if (it + 3 < NIT) { load_stage((it + 3) & (NSTAGE - 1), kbase + (it + 3) * 32); CP_COMMIT(); }

        const uint32_t sb = (uint32_t)((it & (NSTAGE - 1)) * ST1_BYTES);
#pragma unroll
        for (int ks = 0; ks < 2; ks++) {
            const uint32_t oA = sb + ks * 32;             // +16 k elems * 2B
            const uint32_t oB = sb + ks * 16 * SKX * 2;   // +16 k rows
            uint32_t af[4][4];
#pragma unroll
            for (int mt = 0; mt < 4; mt++) ldsm_x4(af[mt], aA[mt] + oA);
            uint32_t bfr[4][4];
#pragma unroll
            for (int nh = 0; nh < 4; nh++) ldsm_x4t(bfr[nh], aB[nh] + oB);
#pragma unroll
            for (int mt = 0; mt < 4; mt++)
#pragma unroll
                for (int nt = 0; nt < 8; nt++)
                    mma16816(acc[mt][nt], af[mt], bfr[nt >> 1][(nt & 1) * 2],
                             bfr[nt >> 1][(nt & 1) * 2 + 1]);
        }
    }

    // epilogue: f32 partial stores
    const int tq = lane >> 2, tr = lane & 3;
    float* PfZ = Pf + (size_t)blockIdx.z * CTX * D;
#pragma unroll
    for (int mt = 0; mt < 4; mt++) {
#pragma unroll
        for (int nt = 0; nt < 8; nt++) {
            int row0 = c0 + wm + mt * 16 + tq;
            int col = j0 + wn + nt * 8 + tr * 2;
            *(float2*)&PfZ[(size_t)row0 * D + col] = make_float2(acc[mt][nt][0], acc[mt][nt][1]);
            *(float2*)&PfZ[(size_t)(row0 + 8) * D + col] = make_float2(acc[mt][nt][2], acc[mt][nt][3]);
        }
    }
}

// ---------------------------------------------------------------------------
// GEMM2: out[i][j] = W[i][j] - scale * sum_c K[c][i] P[c][j]
// A = Kb [k][m] (trans), B = P [k][n] (trans).
// CTA 128x128, 128 thr, 4 warps 2x2, warp tile 64x64.  grid (32,32)
// ---------------------------------------------------------------------------
__global__ __launch_bounds__(128) void gemm2_mma(
    const __nv_bfloat16* __restrict__ Kb, const __nv_bfloat16* __restrict__ P,
    const float* __restrict__ Wmat, float* __restrict__ Out, float scale)
{
    extern __shared__ __align__(16) char sm[];
    const int tid = threadIdx.x, lane = tid & 31, wid = tid >> 5;
    const int j0 = blockIdx.x * 128, i0 = blockIdx.y * 128;
    const int wm = (wid >> 1) * 64, wn = (wid & 1) * 64;

    float acc[4][8][4];
#pragma unroll
    for (int mt = 0; mt < 4; mt++)
#pragma unroll
        for (int nt = 0; nt < 8; nt++)
#pragma unroll
            for (int e = 0; e < 4; e++) acc[mt][nt][e] = 0.f;

    auto load_stage = [&](int stage, int k0) {
        char* tA = sm + stage * ST2_BYTES;
        char* tB = tA + 32 * SKX * 2;
#pragma unroll
        for (int i = 0; i < 4; i++) {
            int c = tid + i * 128;
            int kk = c >> 4, part = c & 15;
            CP16(smem_u32(tA + (kk * SKX + part * 8) * 2),
                 Kb + (size_t)(k0 + kk) * D + i0 + part * 8);
        }
#pragma unroll
        for (int i = 0; i < 4; i++) {
            int c = tid + i * 128;
            int kk = c >> 4, part = c & 15;
            CP16(smem_u32(tB + (kk * SKX + part * 8) * 2),
                 P + (size_t)(k0 + kk) * D + j0 + part * 8);
        }
    };

    // hoisted fragment addresses (stage 0, ks 0); both operands trans
    const uint32_t smb = smem_u32(sm);
    const int krow0 = (lane & 7) + ((lane >> 3) & 1) * 8;
    uint32_t aA[4], aB[4];
#pragma unroll
    for (int mt = 0; mt < 4; mt++) {
        int mcol = wm + mt * 16 + ((lane >> 3) & 1) * 8;
        int krA = (lane & 7) + ((lane >> 4) & 1) * 8;
        aA[mt] = smb + (krA * SKX + mcol) * 2;
    }
#pragma unroll
    for (int nh = 0; nh < 4; nh++) {
        int ncol = wn + nh * 16 + ((lane >> 4) & 1) * 8;
        aB[nh] = smb + 32 * SKX * 2 + (krow0 * SKX + ncol) * 2;
    }

    const int NIT = CTX / 32;  // 16
    load_stage(0, 0); CP_COMMIT();
    load_stage(1, 32); CP_COMMIT();
    load_stage(2, 64); CP_COMMIT();

#pragma unroll 1
    for (int it = 0; it < NIT; it++) {
        if (it < NIT - 2) CP_WAIT2(); else CP_WAIT0();
        __syncthreads();
        if (it + 3 < NIT) { load_stage((it + 3) & (NSTAGE - 1), (it + 3) * 32); CP_COMMIT(); }

        const uint32_t sb = (uint32_t)((it & (NSTAGE - 1)) * ST2_BYTES);
#pragma unroll
        for (int ks = 0; ks < 2; ks++) {
            const uint32_t oK = sb + ks * 16 * SKX * 2;
            uint32_t af[4][4];
#pragma unroll
            for (int mt = 0; mt < 4; mt++) ldsm_x4t(af[mt], aA[mt] + oK);
            uint32_t bfr[4][4];
#pragma unroll
            for (int nh = 0; nh < 4; nh++) ldsm_x4t(bfr[nh], aB[nh] + oK);
#pragma unroll
            for (int mt = 0; mt < 4; mt++)
#pragma unroll
                for (int nt = 0; nt < 8; nt++)
                    mma16816(acc[mt][nt], af[mt], bfr[nt >> 1][(nt & 1) * 2],
                             bfr[nt >> 1][(nt & 1) * 2 + 1]);
        }
    }

    // epilogue: out = W - scale * acc
    const int tq = lane >> 2, tr = lane & 3;
#pragma unroll
    for (int mt = 0; mt < 4; mt++) {
#pragma unroll
        for (int nt = 0; nt < 8; nt++) {
            int row0 = i0 + wm + mt * 16 + tq;
            int col = j0 + wn + nt * 8 + tr * 2;
            float2 w0 = *(const float2*)&Wmat[(size_t)row0 * D + col];
            float2 w1 = *(const float2*)&Wmat[(size_t)(row0 + 8) * D + col];
            float2 o0, o1;
            o0.x = w0.x - scale * acc[mt][nt][0];
            o0.y = w0.y - scale * acc[mt][nt][1];
            o1.x = w1.x - scale * acc[mt][nt][2];
            o1.y = w1.y - scale * acc[mt][nt][3];
            *(float2*)&Out[(size_t)row0 * D + col] = o0;
            *(float2*)&Out[(size_t)(row0 + 8) * D + col] = o1;
        }
    }
}

// ---------------------------------------------------------------------------
// launch
// ---------------------------------------------------------------------------
extern "C" void kernel_launch(void* const* d_in, const int* in_sizes, int n_in,
                              void* d_out, int out_size)
{
    const float* Wmat = (const float*)d_in[0];
    const float* Kmat = (const float*)d_in[1];
    const float* Vmat = (const float*)d_in[2];
    float* Out = (float*)d_out;

    __nv_bfloat16 *Kb, *Wb, *P;
    float* Pf;
    cudaGetSymbolAddress((void**)&Kb, g_Kb);
    cudaGetSymbolAddress((void**)&Wb, g_Wb);
    cudaGetSymbolAddress((void**)&P, g_P);
    cudaGetSymbolAddress((void**)&Pf, g_Pf);

    const float scale = 2.0f * 0.1f / ((float)CTX * (float)D);

    const int S1 = NSTAGE * ST1_BYTES;  // 75776
    const int S2 = NSTAGE * ST2_BYTES;  // 69632
    cudaFuncSetAttribute(gemm1_mma_sk, cudaFuncAttributeMaxDynamicSharedMemorySize, S1);
    cudaFuncSetAttribute(gemm2_mma, cudaFuncAttributeMaxDynamicSharedMemorySize, S2);

    convert_kernel<<<(CTX * D) / (256 * 8), 256>>>((const float4*)Kmat, (__nv_bfloat162*)Kb);
    convert_kernel<<<(D * (size_t)D) / (256 * 8), 256>>>((const float4*)Wmat, (__nv_bfloat162*)Wb);

    gemm1_mma_sk<<<dim3(D / 128, CTX / 128, SPLITK), 128, S1>>>(Kb, Wb, Pf);
    reduce_p_kernel<<<(CTX * D / 4) / 256, 256>>>((const float4*)Pf, (const float4*)Vmat,
                                                  (__nv_bfloat162*)P);
    gemm2_mma<<<dim3(D / 128, D / 128), 128, S2>>>(Kb, P, Wmat, Out, scale);
}